// round 11
// baseline (speedup 1.0000x reference)
#include <cuda_runtime.h>
#include <mma.h>
#include <cstdint>
#include <cstddef>

using namespace nvcuda;

// Problem dims
#define BB   64
#define TT   512
#define DD   512
#define HH   1024
#define OO   512
#define LL   2
#define G3   (3 * HH)          // 3072
#define BT   (BB * TT)         // 32768

#define NBLK  128              // persistent blocks (64 per direction)
#define NBLKD 64               // blocks per direction

// ---------------------------------------------------------------------------
// Scratch (static device memory; allocation-free per harness rules)
// ---------------------------------------------------------------------------
__device__ float g_gx[2][(size_t)BT * G3];       // per-dir input gates [BT, 3H]
__device__ float g_y0[2][(size_t)BT * HH];       // layer-0 outputs per dir
__device__ float g_y1[2][(size_t)BT * HH];       // layer-1 outputs per dir
__device__ float g_h[2][2][HH * BB];             // TRANSPOSED h: [dir][parity][k][m]
__device__ unsigned g_bar_count[2];
__device__ unsigned g_bar_epoch[2];

__global__ void reset_bar()
{
    g_bar_count[0] = 0; g_bar_count[1] = 0;
    g_bar_epoch[0] = 0; g_bar_epoch[1] = 0;
}

__device__ __forceinline__ float4 tf32x4(float4 v)
{
    return make_float4(wmma::__float_to_tf32(v.x), wmma::__float_to_tf32(v.y),
                       wmma::__float_to_tf32(v.z), wmma::__float_to_tf32(v.w));
}

__device__ __forceinline__ void mma_tf32(float& c0, float& c1, float& c2, float& c3,
                                         uint32_t a0, uint32_t a1, uint32_t a2,
                                         uint32_t a3, uint32_t b0, uint32_t b1)
{
    asm volatile("mma.sync.aligned.m16n8k8.row.col.f32.tf32.tf32.f32 "
                 "{%0,%1,%2,%3}, {%4,%5,%6,%7}, {%8,%9}, {%0,%1,%2,%3};"
                 : "+f"(c0), "+f"(c1), "+f"(c2), "+f"(c3)
                 : "r"(a0), "r"(a1), "r"(a2), "r"(a3), "r"(b0), "r"(b1));
}

// ---------------------------------------------------------------------------
// Generic TF32 WMMA GEMM: C[M,N] (+)= A[M,K] @ B[K,N]   (unchanged)
// ---------------------------------------------------------------------------
__global__ void __launch_bounds__(256, 2)
gemm_tf32(const float* __restrict__ A, const float* __restrict__ Bg,
          float* __restrict__ C, int M, int N, int K, int accumulate)
{
    __shared__ float As[16][132];
    __shared__ float Bs[16][132];

    const int bm   = blockIdx.y * 128;
    const int bn   = blockIdx.x * 128;
    const int tid  = threadIdx.x;
    const int warp = tid >> 5;
    const int wm   = (warp & 3) * 32;
    const int wn   = (warp >> 2) * 64;

    wmma::fragment<wmma::accumulator, 16, 16, 8, float> acc[2][4];
#pragma unroll
    for (int i = 0; i < 2; i++)
#pragma unroll
        for (int j = 0; j < 4; j++)
            wmma::fill_fragment(acc[i][j], 0.0f);

    const int lm  = tid & 127;
    const int lkh = (tid >> 7) * 8;
    const int bk0 = (tid + 0 * 256) >> 5, bn0 = ((tid + 0 * 256) & 31) * 4;
    const int bk1 = (tid + 1 * 256) >> 5, bn1 = ((tid + 1 * 256) & 31) * 4;

    const float* ap0 = A + (size_t)(bm + lm) * K + lkh;
    float4 ra0 = *(const float4*)(ap0);
    float4 ra1 = *(const float4*)(ap0 + 4);
    float4 rb0 = *(const float4*)(Bg + (size_t)bk0 * N + bn + bn0);
    float4 rb1 = *(const float4*)(Bg + (size_t)bk1 * N + bn + bn1);

    for (int k0 = 0; k0 < K; k0 += 16) {
        float4 a0 = tf32x4(ra0), a1 = tf32x4(ra1);
        As[lkh + 0][lm] = a0.x; As[lkh + 1][lm] = a0.y;
        As[lkh + 2][lm] = a0.z; As[lkh + 3][lm] = a0.w;
        As[lkh + 4][lm] = a1.x; As[lkh + 5][lm] = a1.y;
        As[lkh + 6][lm] = a1.z; As[lkh + 7][lm] = a1.w;
        *(float4*)&Bs[bk0][bn0] = tf32x4(rb0);
        *(float4*)&Bs[bk1][bn1] = tf32x4(rb1);
        __syncthreads();

        if (k0 + 16 < K) {
            const float* apn = ap0 + k0 + 16;
            ra0 = *(const float4*)(apn);
            ra1 = *(const float4*)(apn + 4);
            rb0 = *(const float4*)(Bg + (size_t)(k0 + 16 + bk0) * N + bn + bn0);
            rb1 = *(const float4*)(Bg + (size_t)(k0 + 16 + bk1) * N + bn + bn1);
        }

#pragma unroll
        for (int kk = 0; kk < 16; kk += 8) {
            wmma::fragment<wmma::matrix_a, 16, 16, 8, wmma::precision::tf32,
                           wmma::col_major> af[2];
#pragma unroll
            for (int i = 0; i < 2; i++)
                wmma::load_matrix_sync(af[i], &As[kk][wm + i * 16], 132);
#pragma unroll
            for (int j = 0; j < 4; j++) {
                wmma::fragment<wmma::matrix_b, 16, 16, 8, wmma::precision::tf32,
                               wmma::row_major> bf;
                wmma::load_matrix_sync(bf, &Bs[kk][wn + j * 16], 132);
#pragma unroll
                for (int i = 0; i < 2; i++)
                    wmma::mma_sync(acc[i][j], af[i], bf, acc[i][j]);
            }
        }
        __syncthreads();
    }

#pragma unroll
    for (int i = 0; i < 2; i++)
#pragma unroll
        for (int j = 0; j < 4; j++) {
            float* cp = C + (size_t)(bm + wm + i * 16) * N + bn + wn + j * 16;
            if (accumulate) {
                wmma::fragment<wmma::accumulator, 16, 16, 8, float> cf;
                wmma::load_matrix_sync(cf, cp, N, wmma::mem_row_major);
#pragma unroll
                for (int e = 0; e < cf.num_elements; e++)
                    acc[i][j].x[e] += cf.x[e];
            }
            wmma::store_matrix_sync(cp, acc[i][j], N, wmma::mem_row_major);
        }
}

// ---------------------------------------------------------------------------
// Persistent GRU layer kernel v7: 512 threads (16 warps = k4 x m4).
// Same per-SM totals as v6 but 2x warps for latency hiding. Each warp:
// 16m x 48n x 256k partial; per chunk 1 LDG.128 + 1 STS.128 + 4 LDS.32 (A)
// + 3 ldmatrix.x4 (B) + 6 mma.m16n8k8. Staging buffer [8k][stride 24]
// (A-frag LDS conflict-free). Reduction/pointwise on 512 threads.
// ---------------------------------------------------------------------------
#define WHS_LD  1028                 // floats per WhsT row
#define WHS_F   (48 * WHS_LD)        // 49344 floats
#define STG_STRIDE 24                // staging row stride (banks 8*lt apart)
#define STG_WARP   (2 * 8 * STG_STRIDE)  // 384 floats per warp (double buffer)
#define OVL_F   6144                 // staging (16*384=6144) / partials (6144)
#define SMEM_BYTES ((WHS_F + OVL_F) * 4)   // 221952 B

__device__ __forceinline__ void grid_barrier_dir(int dir, unsigned e)
{
    __syncthreads();
    if (threadIdx.x == 0) {
        __threadfence();
        unsigned arr = atomicAdd(&g_bar_count[dir], 1u);
        if (arr == e * NBLKD - 1u) {
            atomicExch(&g_bar_epoch[dir], e);
        } else {
            while (*(volatile unsigned*)&g_bar_epoch[dir] < e) __nanosleep(32);
        }
        __threadfence();
    }
    __syncthreads();
}

__global__ void __launch_bounds__(512, 1)
gru_layer(const float* __restrict__ Wh_fw, const float* __restrict__ Wh_bw,
          const float* __restrict__ bx_fw, const float* __restrict__ bh_fw,
          const float* __restrict__ bx_bw, const float* __restrict__ bh_bw,
          float* __restrict__ y_fw, float* __restrict__ y_bw)
{
    extern __shared__ float smem[];
    float* WhsT = smem;            // [48][1028] tf32, WhsT[n][k]
    float* XB   = smem + WHS_F;    // overlay: staging / partial regions

    const int bid = blockIdx.x;
    const int dir = bid >> 6;          // 0 = fw, 1 = bw
    const int c0  = (bid & 63) * 16;   // h-column base

    const float* Wh = dir ? Wh_bw : Wh_fw;
    const float* bx = dir ? bx_bw : bx_fw;
    const float* bh = dir ? bh_bw : bh_fw;
    float*       y  = dir ? y_bw  : y_fw;
    const float* gx = g_gx[dir];

    const int tid  = threadIdx.x;
    const int warp = tid >> 5;
    const int lane = tid & 31;
    const int ki   = warp >> 2;        // k quarter (256)
    const int mi   = warp & 3;         // m quarter (16 rows)
    const int lg   = lane >> 2;        // mma groupID
    const int lt   = lane & 3;         // mma threadID-in-group

    float* mybuf = XB + warp * STG_WARP;   // 2 x [8k][24] private staging

    const uint32_t whs_u32 = (uint32_t)__cvta_generic_to_shared(WhsT);
    const int lmg = lane >> 3;
    const int lmr = lane & 7;
    uint32_t ldm_off[3];
#pragma unroll
    for (int q = 0; q < 3; q++)
        ldm_off[q] = (uint32_t)((q * 16 + ((lmg >> 1) & 1) * 8 + lmr) * WHS_LD
                                + (lmg & 1) * 4);

    // ---- stage WhT slice into SMEM, tf32-rounded (once) ----
    for (int i = tid; i < 48 * HH; i += 512) {
        int k = i / 48;
        int n = i - k * 48;
        WhsT[n * WHS_LD + k] =
            wmma::__float_to_tf32(Wh[(size_t)k * G3 + (n >> 4) * HH + c0 + (n & 15)]);
    }

    // ---- per-thread pointwise constants: (pm, 2 cols at pj) ----
    const int pm  = tid >> 3;          // batch row (0..63)
    const int pj  = (tid & 7) * 2;     // 2 consecutive cols
    const int phc = c0 + pj;
    float br[2], bz[2], bxn_[2], bhn_[2];
#pragma unroll
    for (int q = 0; q < 2; q++) {
        int hc = phc + q;
        br[q]   = bx[hc] + bh[hc];
        bz[q]   = bx[HH + hc] + bh[HH + hc];
        bxn_[q] = bx[2 * HH + hc];
        bhn_[q] = bh[2 * HH + hc];
    }
    __syncthreads();

    // staging coords within a warp's [8k][16m] chunk
    const int sk = lane >> 2;          // 0..7  (k within chunk)
    const int sm = (lane & 3) * 4;     // m offset within 16

    for (int s = 0; s < TT; s++) {
        const int t = dir ? (TT - 1 - s) : s;
        const float* hT  = g_h[dir][(s + 1) & 1];   // h_{s-1}, [k][64]
        float*       hTw = g_h[dir][s & 1];         // h_s

        // ---- pointwise prefetch ----
        float2 pxr, pxz, pxn, php;
        {
            const float* gp = gx + ((size_t)pm * TT + t) * G3 + phc;
            pxr = __ldcs((const float2*)gp);
            pxz = __ldcs((const float2*)(gp + HH));
            pxn = __ldcs((const float2*)(gp + 2 * HH));
            if (s > 0) {
                const int tp = dir ? (t + 1) : (t - 1);
                php = *(const float2*)(y + ((size_t)pm * TT + tp) * HH + phc);
            } else {
                php = make_float2(0.f, 0.f);
            }
        }

        float acc[6][4];
#pragma unroll
        for (int n = 0; n < 6; n++)
#pragma unroll
            for (int e = 0; e < 4; e++)
                acc[n][e] = 0.f;

        if (s > 0) {
            const float* hsrc = hT + (size_t)(ki * 256 + sk) * BB + mi * 16 + sm;
            float4 P[3];
#pragma unroll
            for (int c = 0; c < 3; c++)
                P[c] = __ldcg((const float4*)(hsrc + c * 8 * BB));
            *(float4*)(mybuf + sk * STG_STRIDE + sm) = P[0];
            __syncwarp();

#pragma unroll
            for (int c = 0; c < 32; c++) {
                if (c < 31)
                    *(float4*)(mybuf + ((c + 1) & 1) * 192 + sk * STG_STRIDE + sm)
                        = P[(c + 1) % 3];
                if (c < 29)
                    P[c % 3] = __ldcg((const float4*)(hsrc + (c + 3) * 8 * BB));

                // ---- A fragments (4 scalar LDS, conflict-free @ stride 24) ----
                const float* bp = mybuf + (c & 1) * 192;
                uint32_t a0 = __float_as_uint(bp[lt * STG_STRIDE + lg]);
                uint32_t a1 = __float_as_uint(bp[lt * STG_STRIDE + lg + 8]);
                uint32_t a2 = __float_as_uint(bp[(lt + 4) * STG_STRIDE + lg]);
                uint32_t a3 = __float_as_uint(bp[(lt + 4) * STG_STRIDE + lg + 8]);

                // ---- B fragments: 3x ldmatrix.x4 on WhsT rows ----
                const uint32_t kb = (uint32_t)(ki * 256 + c * 8);
                uint32_t b[3][4];
#pragma unroll
                for (int q = 0; q < 3; q++) {
                    uint32_t addr = whs_u32 + (ldm_off[q] + kb) * 4u;
                    asm volatile(
                        "ldmatrix.sync.aligned.m8n8.x4.shared.b16 "
                        "{%0,%1,%2,%3}, [%4];"
                        : "=r"(b[q][0]), "=r"(b[q][1]), "=r"(b[q][2]), "=r"(b[q][3])
                        : "r"(addr));
                }

                // ---- 6 mma.m16n8k8 ----
#pragma unroll
                for (int n = 0; n < 6; n++)
                    mma_tf32(acc[n][0], acc[n][1], acc[n][2], acc[n][3],
                             a0, a1, a2, a3,
                             b[n >> 1][(n & 1) * 2], b[n >> 1][(n & 1) * 2 + 1]);
                __syncwarp();
            }
        }
        __syncthreads();   // staging done; overlay becomes partial regions

        // ---- pairwise k pre-reduction into 2 regions ----
        // D element: row = mi*16 + lg (+8), col = n*8 + 2*lt (+1)
        if (ki >= 2) {
            float* dst = XB + (ki - 2) * 3072;
#pragma unroll
            for (int n = 0; n < 6; n++) {
                float* p = dst + (mi * 16 + lg) * 48 + n * 8 + 2 * lt;
                *(float2*)p           = make_float2(acc[n][0], acc[n][1]);
                *(float2*)(p + 8 * 48) = make_float2(acc[n][2], acc[n][3]);
            }
        }
        __syncthreads();
        if (ki < 2) {
            float* dst = XB + ki * 3072;
#pragma unroll
            for (int n = 0; n < 6; n++) {
                float* p = dst + (mi * 16 + lg) * 48 + n * 8 + 2 * lt;
                float2 lo = *(float2*)p;
                float2 hi = *(float2*)(p + 8 * 48);
                lo.x += acc[n][0]; lo.y += acc[n][1];
                hi.x += acc[n][2]; hi.y += acc[n][3];
                *(float2*)p            = lo;
                *(float2*)(p + 8 * 48) = hi;
            }
        }
        __syncthreads();

        // ---- pointwise GRU update: thread -> (pm, 2 cols at pj) ----
        {
            const float* Gr = XB + pm * 48 + pj;
            float2 gr0 = *(const float2*)(Gr);
            float2 gr1 = *(const float2*)(Gr + 3072);
            float2 gz0 = *(const float2*)(Gr + 16);
            float2 gz1 = *(const float2*)(Gr + 16 + 3072);
            float2 gn0 = *(const float2*)(Gr + 32);
            float2 gn1 = *(const float2*)(Gr + 32 + 3072);

            float hv[2];
#pragma unroll
            for (int q = 0; q < 2; q++) {
                float gr = ((const float*)&gr0)[q] + ((const float*)&gr1)[q];
                float gz = ((const float*)&gz0)[q] + ((const float*)&gz1)[q];
                float gn = ((const float*)&gn0)[q] + ((const float*)&gn1)[q];
                float xr = ((const float*)&pxr)[q];
                float xz = ((const float*)&pxz)[q];
                float xn = ((const float*)&pxn)[q];
                float hp = ((const float*)&php)[q];
                float r = 1.f / (1.f + __expf(-(xr + br[q] + gr)));
                float z = 1.f / (1.f + __expf(-(xz + bz[q] + gz)));
                float n = tanhf(xn + bxn_[q] + r * (gn + bhn_[q]));
                hv[q] = (1.f - z) * n + z * hp;
            }
            *(float2*)(y + ((size_t)pm * TT + t) * HH + phc) =
                make_float2(hv[0], hv[1]);
#pragma unroll
            for (int q = 0; q < 2; q++)
                __stcg(&hTw[(size_t)(phc + q) * BB + pm],
                       wmma::__float_to_tf32(hv[q]));
        }

        grid_barrier_dir(dir, (unsigned)(s + 1));
    }
}

// ---------------------------------------------------------------------------
// FC bias prefill + final-hidden extraction
// ---------------------------------------------------------------------------
__global__ void fill_bias(float* __restrict__ out, const float* __restrict__ b)
{
    size_t i = (size_t)blockIdx.x * blockDim.x + threadIdx.x;
    if (i < (size_t)BT * OO) out[i] = b[i & (OO - 1)];
}

__global__ void write_finals(float* __restrict__ out)
{
    int i = blockIdx.x * blockDim.x + threadIdx.x;  // 0 .. 2*L*B*H-1
    int j = i & (HH - 1);
    int b = (i >> 10) & (BB - 1);
    int l = (i >> 16) & 1;
    int d = i >> 17;                                 // 0 = fw_h, 1 = bw_h
    const float* y = (l == 0) ? g_y0[d] : g_y1[d];
    int t = d ? 0 : (TT - 1);
    out[(size_t)BT * OO + i] = y[((size_t)b * TT + t) * HH + j];
}

// ---------------------------------------------------------------------------
// Launch sequence (graph-capturable: ~12 kernel launches, no allocs)
// ---------------------------------------------------------------------------
extern "C" void kernel_launch(void* const* d_in, const int* in_sizes, int n_in,
                              void* d_out, int out_size)
{
    const float* x       = (const float*)d_in[0];
    const float* fw_Wx0  = (const float*)d_in[1];
    const float* fw_Wh0  = (const float*)d_in[2];
    const float* fw_bx0  = (const float*)d_in[3];
    const float* fw_bh0  = (const float*)d_in[4];
    const float* fw_Wx1  = (const float*)d_in[5];
    const float* fw_Wh1  = (const float*)d_in[6];
    const float* fw_bx1  = (const float*)d_in[7];
    const float* fw_bh1  = (const float*)d_in[8];
    const float* bw_Wx0  = (const float*)d_in[9];
    const float* bw_Wh0  = (const float*)d_in[10];
    const float* bw_bx0  = (const float*)d_in[11];
    const float* bw_bh0  = (const float*)d_in[12];
    const float* bw_Wx1  = (const float*)d_in[13];
    const float* bw_Wh1  = (const float*)d_in[14];
    const float* bw_bx1  = (const float*)d_in[15];
    const float* bw_bh1  = (const float*)d_in[16];
    const float* fc_W    = (const float*)d_in[17];
    const float* fc_b    = (const float*)d_in[18];
    float* out = (float*)d_out;

    cudaFuncSetAttribute(gru_layer, cudaFuncAttributeMaxDynamicSharedMemorySize,
                         SMEM_BYTES);

    void* p;
    cudaGetSymbolAddress(&p, g_gx);
    float* gx0 = (float*)p;
    float* gx1 = gx0 + (size_t)BT * G3;
    cudaGetSymbolAddress(&p, g_y0);
    float* y00 = (float*)p;
    float* y01 = y00 + (size_t)BT * HH;
    cudaGetSymbolAddress(&p, g_y1);
    float* y10 = (float*)p;
    float* y11 = y10 + (size_t)BT * HH;

    dim3 ggx(G3 / 128, BT / 128);   // (24, 256)
    dim3 gfc(OO / 128, BT / 128);   // (4, 256)

    // Layer 0 input gates
    gemm_tf32<<<ggx, 256>>>(x, fw_Wx0, gx0, BT, G3, DD, 0);
    gemm_tf32<<<ggx, 256>>>(x, bw_Wx0, gx1, BT, G3, DD, 0);

    // Layer 0 recurrence (persistent, both dirs)
    reset_bar<<<1, 1>>>();
    gru_layer<<<NBLK, 512, SMEM_BYTES>>>(fw_Wh0, bw_Wh0, fw_bx0, fw_bh0,
                                         bw_bx0, bw_bh0, y00, y01);

    // Layer 1 input gates
    gemm_tf32<<<ggx, 256>>>(y00, fw_Wx1, gx0, BT, G3, HH, 0);
    gemm_tf32<<<ggx, 256>>>(y01, bw_Wx1, gx1, BT, G3, HH, 0);

    // Layer 1 recurrence
    reset_bar<<<1, 1>>>();
    gru_layer<<<NBLK, 512, SMEM_BYTES>>>(fw_Wh1, bw_Wh1, fw_bx1, fw_bh1,
                                         bw_bx1, bw_bh1, y10, y11);

    // FC: out = [fw_y1, bw_y1] @ fc_W + fc_b  (split-K over the two halves)
    fill_bias<<<((size_t)BT * OO + 255) / 256, 256>>>(out, fc_b);
    gemm_tf32<<<gfc, 256>>>(y10, fc_W,                   out, BT, OO, HH, 1);
    gemm_tf32<<<gfc, 256>>>(y11, fc_W + (size_t)HH * OO, out, BT, OO, HH, 1);

    // Final hidden states: fw_h [L,B,H] then bw_h [L,B,H]
    write_finals<<<(2 * LL * BB * HH) / 256, 256>>>(out);
}

// round 12
// speedup vs baseline: 1.0731x; 1.0731x over previous
#include <cuda_runtime.h>
#include <mma.h>
#include <cstdint>
#include <cstddef>

using namespace nvcuda;

// Problem dims
#define BB   64
#define TT   512
#define DD   512
#define HH   1024
#define OO   512
#define LL   2
#define G3   (3 * HH)          // 3072
#define BT   (BB * TT)         // 32768

#define NBLK  128              // persistent blocks (64 per direction)
#define NBLKD 64               // blocks per direction

// ---------------------------------------------------------------------------
// Scratch (static device memory; allocation-free per harness rules)
// ---------------------------------------------------------------------------
__device__ float g_gx[2][(size_t)BT * G3];       // per-dir input gates [BT, 3H]
__device__ float g_y0[2][(size_t)BT * HH];       // layer-0 outputs per dir
__device__ float g_y1[2][(size_t)BT * HH];       // layer-1 outputs per dir
__device__ float g_h[2][2][HH * BB];             // TRANSPOSED h: [dir][parity][k][m]
// monotonic sync counters, each on its own 128B line
__device__ unsigned g_stage_done[2][32];         // [dir][0]: blocks-finished-staging
__device__ unsigned g_h_ready[2][4][32];         // [dir][quarter][0]: h writes

__global__ void reset_bar()
{
    for (int d = 0; d < 2; d++) {
        g_stage_done[d][0] = 0;
        for (int q = 0; q < 4; q++) g_h_ready[d][q][0] = 0;
    }
}

__device__ __forceinline__ float4 tf32x4(float4 v)
{
    return make_float4(wmma::__float_to_tf32(v.x), wmma::__float_to_tf32(v.y),
                       wmma::__float_to_tf32(v.z), wmma::__float_to_tf32(v.w));
}

__device__ __forceinline__ void mma_tf32(float& c0, float& c1, float& c2, float& c3,
                                         uint32_t a0, uint32_t a1, uint32_t a2,
                                         uint32_t a3, uint32_t b0, uint32_t b1)
{
    asm volatile("mma.sync.aligned.m16n8k8.row.col.f32.tf32.tf32.f32 "
                 "{%0,%1,%2,%3}, {%4,%5,%6,%7}, {%8,%9}, {%0,%1,%2,%3};"
                 : "+f"(c0), "+f"(c1), "+f"(c2), "+f"(c3)
                 : "r"(a0), "r"(a1), "r"(a2), "r"(a3), "r"(b0), "r"(b1));
}

// ---------------------------------------------------------------------------
// Generic TF32 WMMA GEMM: C[M,N] (+)= A[M,K] @ B[K,N]   (unchanged)
// ---------------------------------------------------------------------------
__global__ void __launch_bounds__(256, 2)
gemm_tf32(const float* __restrict__ A, const float* __restrict__ Bg,
          float* __restrict__ C, int M, int N, int K, int accumulate)
{
    __shared__ float As[16][132];
    __shared__ float Bs[16][132];

    const int bm   = blockIdx.y * 128;
    const int bn   = blockIdx.x * 128;
    const int tid  = threadIdx.x;
    const int warp = tid >> 5;
    const int wm   = (warp & 3) * 32;
    const int wn   = (warp >> 2) * 64;

    wmma::fragment<wmma::accumulator, 16, 16, 8, float> acc[2][4];
#pragma unroll
    for (int i = 0; i < 2; i++)
#pragma unroll
        for (int j = 0; j < 4; j++)
            wmma::fill_fragment(acc[i][j], 0.0f);

    const int lm  = tid & 127;
    const int lkh = (tid >> 7) * 8;
    const int bk0 = (tid + 0 * 256) >> 5, bn0 = ((tid + 0 * 256) & 31) * 4;
    const int bk1 = (tid + 1 * 256) >> 5, bn1 = ((tid + 1 * 256) & 31) * 4;

    const float* ap0 = A + (size_t)(bm + lm) * K + lkh;
    float4 ra0 = *(const float4*)(ap0);
    float4 ra1 = *(const float4*)(ap0 + 4);
    float4 rb0 = *(const float4*)(Bg + (size_t)bk0 * N + bn + bn0);
    float4 rb1 = *(const float4*)(Bg + (size_t)bk1 * N + bn + bn1);

    for (int k0 = 0; k0 < K; k0 += 16) {
        float4 a0 = tf32x4(ra0), a1 = tf32x4(ra1);
        As[lkh + 0][lm] = a0.x; As[lkh + 1][lm] = a0.y;
        As[lkh + 2][lm] = a0.z; As[lkh + 3][lm] = a0.w;
        As[lkh + 4][lm] = a1.x; As[lkh + 5][lm] = a1.y;
        As[lkh + 6][lm] = a1.z; As[lkh + 7][lm] = a1.w;
        *(float4*)&Bs[bk0][bn0] = tf32x4(rb0);
        *(float4*)&Bs[bk1][bn1] = tf32x4(rb1);
        __syncthreads();

        if (k0 + 16 < K) {
            const float* apn = ap0 + k0 + 16;
            ra0 = *(const float4*)(apn);
            ra1 = *(const float4*)(apn + 4);
            rb0 = *(const float4*)(Bg + (size_t)(k0 + 16 + bk0) * N + bn + bn0);
            rb1 = *(const float4*)(Bg + (size_t)(k0 + 16 + bk1) * N + bn + bn1);
        }

#pragma unroll
        for (int kk = 0; kk < 16; kk += 8) {
            wmma::fragment<wmma::matrix_a, 16, 16, 8, wmma::precision::tf32,
                           wmma::col_major> af[2];
#pragma unroll
            for (int i = 0; i < 2; i++)
                wmma::load_matrix_sync(af[i], &As[kk][wm + i * 16], 132);
#pragma unroll
            for (int j = 0; j < 4; j++) {
                wmma::fragment<wmma::matrix_b, 16, 16, 8, wmma::precision::tf32,
                               wmma::row_major> bf;
                wmma::load_matrix_sync(bf, &Bs[kk][wn + j * 16], 132);
#pragma unroll
                for (int i = 0; i < 2; i++)
                    wmma::mma_sync(acc[i][j], af[i], bf, acc[i][j]);
            }
        }
        __syncthreads();
    }

#pragma unroll
    for (int i = 0; i < 2; i++)
#pragma unroll
        for (int j = 0; j < 4; j++) {
            float* cp = C + (size_t)(bm + wm + i * 16) * N + bn + wn + j * 16;
            if (accumulate) {
                wmma::fragment<wmma::accumulator, 16, 16, 8, float> cf;
                wmma::load_matrix_sync(cf, cp, N, wmma::mem_row_major);
#pragma unroll
                for (int e = 0; e < cf.num_elements; e++)
                    acc[i][j].x[e] += cf.x[e];
            }
            wmma::store_matrix_sync(cp, acc[i][j], N, wmma::mem_row_major);
        }
}

// ---------------------------------------------------------------------------
// Persistent GRU layer kernel v8: R8 execution config (256 thr, k4 x m2)
// with fine-grained producer/consumer sync replacing the grid barrier.
//   consumer (per warp, before staging step s): h_ready[dir][ki] >= 16*s
//   producer (per warp, before writing h_s):    stage_done[dir]  >= 64*s
// Monotonic counters allow ~1 step of inter-block skew -> sync latency
// pipelines behind compute.
// ---------------------------------------------------------------------------
#define WHS_LD  1028                 // floats per WhsT row
#define WHS_F   (48 * WHS_LD)        // 49344 floats
#define OVL_F   6144                 // staging (4608) / 2 partial regions (6144)
#define SMEM_BYTES ((WHS_F + OVL_F) * 4)   // 221952 B

__global__ void __launch_bounds__(256, 1)
gru_layer(const float* __restrict__ Wh_fw, const float* __restrict__ Wh_bw,
          const float* __restrict__ bx_fw, const float* __restrict__ bh_fw,
          const float* __restrict__ bx_bw, const float* __restrict__ bh_bw,
          float* __restrict__ y_fw, float* __restrict__ y_bw)
{
    extern __shared__ float smem[];
    float* WhsT = smem;            // [48][1028] tf32, WhsT[n][k]
    float* XB   = smem + WHS_F;    // overlay: staging / partial regions

    const int bid = blockIdx.x;
    const int dir = bid >> 6;          // 0 = fw, 1 = bw
    const int bd  = bid & 63;          // block within direction
    const int c0  = bd * 16;           // h-column base
    const int myq = bd >> 4;           // the k-quarter this block's h-cols feed

    const float* Wh = dir ? Wh_bw : Wh_fw;
    const float* bx = dir ? bx_bw : bx_fw;
    const float* bh = dir ? bh_bw : bh_fw;
    float*       y  = dir ? y_bw  : y_fw;
    const float* gx = g_gx[dir];

    const int tid  = threadIdx.x;
    const int warp = tid >> 5;
    const int lane = tid & 31;
    const int ki   = warp >> 1;        // k quarter (256)
    const int mi   = warp & 1;         // m half (32 rows)
    const int lg   = lane >> 2;        // mma groupID
    const int lt   = lane & 3;         // mma threadID-in-group

    float* mybuf = XB + warp * 576;    // 2 x [8k][36m] private staging

    volatile unsigned* vstage = &g_stage_done[dir][0];
    volatile unsigned* vready = &g_h_ready[dir][ki][0];

    const uint32_t whs_u32 = (uint32_t)__cvta_generic_to_shared(WhsT);
    const int lmg = lane >> 3;
    const int lmr = lane & 7;
    uint32_t ldm_off[3];
#pragma unroll
    for (int q = 0; q < 3; q++)
        ldm_off[q] = (uint32_t)((q * 16 + ((lmg >> 1) & 1) * 8 + lmr) * WHS_LD
                                + (lmg & 1) * 4);

    // ---- stage WhT slice into SMEM, tf32-rounded (once) ----
    for (int i = tid; i < 48 * HH; i += 256) {
        int k = i / 48;
        int n = i - k * 48;
        WhsT[n * WHS_LD + k] =
            wmma::__float_to_tf32(Wh[(size_t)k * G3 + (n >> 4) * HH + c0 + (n & 15)]);
    }

    // ---- per-thread pointwise constants ----
    const int pm  = tid >> 2;          // batch row (0..63)
    const int pj  = (tid & 3) * 4;     // 4 consecutive cols
    const int phc = c0 + pj;
    float br[4], bz[4], bxn_[4], bhn_[4];
#pragma unroll
    for (int q = 0; q < 4; q++) {
        int hc = phc + q;
        br[q]   = bx[hc] + bh[hc];
        bz[q]   = bx[HH + hc] + bh[HH + hc];
        bxn_[q] = bx[2 * HH + hc];
        bhn_[q] = bh[2 * HH + hc];
    }
    __syncthreads();

    // staging coords within a warp's [8k][32m] chunk
    const int sk = lane >> 2;          // 0..7  (k within chunk)
    const int sm = (lane & 3) * 8;     // m offset within 32

    for (int s = 0; s < TT; s++) {
        const int t = dir ? (TT - 1 - s) : s;
        const float* hT  = g_h[dir][(s + 1) & 1];   // h_{s-1}, [k][64]
        float*       hTw = g_h[dir][s & 1];         // h_s

        // ---- pointwise prefetch (own-block y + streaming gx; no sync dep) ----
        float4 pxr, pxz, pxn, php;
        {
            const float* gp = gx + ((size_t)pm * TT + t) * G3 + phc;
            pxr = __ldcs((const float4*)gp);
            pxz = __ldcs((const float4*)(gp + HH));
            pxn = __ldcs((const float4*)(gp + 2 * HH));
            if (s > 0) {
                const int tp = dir ? (t + 1) : (t - 1);
                php = *(const float4*)(y + ((size_t)pm * TT + tp) * HH + phc);
            } else {
                php = make_float4(0.f, 0.f, 0.f, 0.f);
            }
        }

        float acc[2][6][4];
#pragma unroll
        for (int f = 0; f < 2; f++)
#pragma unroll
            for (int n = 0; n < 6; n++)
#pragma unroll
                for (int e = 0; e < 4; e++)
                    acc[f][n][e] = 0.f;

        if (s > 0) {
            // ---- consumer wait: my k-quarter's 16 producers done h_{s-1} ----
            if (lane == 0) {
                const unsigned tgt = 16u * (unsigned)s;
                while (*vready < tgt) __nanosleep(32);
            }
            __syncwarp();

            const float* hsrc = hT + (size_t)(ki * 256 + sk) * BB + mi * 32 + sm;
            float4 P[3][2];
#pragma unroll
            for (int c = 0; c < 3; c++) {
                P[c][0] = __ldcg((const float4*)(hsrc + c * 8 * BB));
                P[c][1] = __ldcg((const float4*)(hsrc + c * 8 * BB + 4));
            }
            {
                float* d = mybuf + sk * 36 + sm;
                *(float4*)(d)     = P[0][0];
                *(float4*)(d + 4) = P[0][1];
            }
            __syncwarp();

#pragma unroll
            for (int c = 0; c < 32; c++) {
                if (c < 31) {
                    float* d = mybuf + ((c + 1) & 1) * 288 + sk * 36 + sm;
                    *(float4*)(d)     = P[(c + 1) % 3][0];
                    *(float4*)(d + 4) = P[(c + 1) % 3][1];
                }
                if (c < 29) {
                    P[c % 3][0] = __ldcg((const float4*)(hsrc + (c + 3) * 8 * BB));
                    P[c % 3][1] = __ldcg((const float4*)(hsrc + (c + 3) * 8 * BB + 4));
                }

                // ---- A fragments (scalar LDS from [k][m] staging) ----
                const float* bp = mybuf + (c & 1) * 288;
                uint32_t a[2][4];
#pragma unroll
                for (int f = 0; f < 2; f++) {
                    a[f][0] = __float_as_uint(bp[lt * 36 + f * 16 + lg]);
                    a[f][1] = __float_as_uint(bp[lt * 36 + f * 16 + lg + 8]);
                    a[f][2] = __float_as_uint(bp[(lt + 4) * 36 + f * 16 + lg]);
                    a[f][3] = __float_as_uint(bp[(lt + 4) * 36 + f * 16 + lg + 8]);
                }

                // ---- B fragments: 3x ldmatrix.x4 on WhsT rows ----
                const uint32_t kb = (uint32_t)(ki * 256 + c * 8);
                uint32_t b[3][4];
#pragma unroll
                for (int q = 0; q < 3; q++) {
                    uint32_t addr = whs_u32 + (ldm_off[q] + kb) * 4u;
                    asm volatile(
                        "ldmatrix.sync.aligned.m8n8.x4.shared.b16 "
                        "{%0,%1,%2,%3}, [%4];"
                        : "=r"(b[q][0]), "=r"(b[q][1]), "=r"(b[q][2]), "=r"(b[q][3])
                        : "r"(addr));
                }

                // ---- 12 mma.m16n8k8 ----
#pragma unroll
                for (int f = 0; f < 2; f++)
#pragma unroll
                    for (int n = 0; n < 6; n++)
                        mma_tf32(acc[f][n][0], acc[f][n][1], acc[f][n][2], acc[f][n][3],
                                 a[f][0], a[f][1], a[f][2], a[f][3],
                                 b[n >> 1][(n & 1) * 2], b[n >> 1][(n & 1) * 2 + 1]);
                __syncwarp();
            }
        }
        __syncthreads();   // staging reads complete; overlay becomes partials

        // this block finished consuming h_{s-1}
        if (tid == 0) atomicAdd(&g_stage_done[dir][0], 1u);

        // ---- pairwise k pre-reduction into 2 regions (raw acc layout) ----
        if (ki >= 2) {
            float* dst = XB + (ki - 2) * 3072;
#pragma unroll
            for (int f = 0; f < 2; f++)
#pragma unroll
                for (int n = 0; n < 6; n++) {
                    float* p = dst + (mi * 32 + f * 16 + lg) * 48 + n * 8 + 2 * lt;
                    *(float2*)p          = make_float2(acc[f][n][0], acc[f][n][1]);
                    *(float2*)(p + 8*48) = make_float2(acc[f][n][2], acc[f][n][3]);
                }
        }
        __syncthreads();
        if (ki < 2) {
            float* dst = XB + ki * 3072;
#pragma unroll
            for (int f = 0; f < 2; f++)
#pragma unroll
                for (int n = 0; n < 6; n++) {
                    float* p = dst + (mi * 32 + f * 16 + lg) * 48 + n * 8 + 2 * lt;
                    float2 lo = *(float2*)p;
                    float2 hi = *(float2*)(p + 8*48);
                    lo.x += acc[f][n][0]; lo.y += acc[f][n][1];
                    hi.x += acc[f][n][2]; hi.y += acc[f][n][3];
                    *(float2*)p          = lo;
                    *(float2*)(p + 8*48) = hi;
                }
        }
        __syncthreads();

        // ---- producer wait: all blocks past staging of step s-1 ----
        if (s > 0) {
            if (lane == 0) {
                const unsigned tgt = 64u * (unsigned)s;
                while (*vstage < tgt) __nanosleep(32);
            }
            __syncwarp();
        }

        // ---- pointwise GRU update: thread -> (pm, 4 cols at pj) ----
        {
            const float* Gr = XB + pm * 48 + pj;
            float4 gr0 = *(const float4*)(Gr);
            float4 gr1 = *(const float4*)(Gr + 3072);
            float4 gz0 = *(const float4*)(Gr + 16);
            float4 gz1 = *(const float4*)(Gr + 16 + 3072);
            float4 gn0 = *(const float4*)(Gr + 32);
            float4 gn1 = *(const float4*)(Gr + 32 + 3072);

            float hv[4];
#pragma unroll
            for (int q = 0; q < 4; q++) {
                float gr = ((const float*)&gr0)[q] + ((const float*)&gr1)[q];
                float gz = ((const float*)&gz0)[q] + ((const float*)&gz1)[q];
                float gn = ((const float*)&gn0)[q] + ((const float*)&gn1)[q];
                float xr = ((const float*)&pxr)[q];
                float xz = ((const float*)&pxz)[q];
                float xn = ((const float*)&pxn)[q];
                float hp = ((const float*)&php)[q];
                float r = 1.f / (1.f + __expf(-(xr + br[q] + gr)));
                float z = 1.f / (1.f + __expf(-(xz + bz[q] + gz)));
                float n = tanhf(xn + bxn_[q] + r * (gn + bhn_[q]));
                hv[q] = (1.f - z) * n + z * hp;
            }
            *(float4*)(y + ((size_t)pm * TT + t) * HH + phc) =
                make_float4(hv[0], hv[1], hv[2], hv[3]);
#pragma unroll
            for (int q = 0; q < 4; q++)
                __stcg(&hTw[(size_t)(phc + q) * BB + pm],
                       wmma::__float_to_tf32(hv[q]));
        }

        // ---- publish h_s for my quarter ----
        __syncthreads();
        if (tid == 0) {
            __threadfence();
            atomicAdd(&g_h_ready[dir][myq][0], 1u);
        }
    }
}

// ---------------------------------------------------------------------------
// FC bias prefill + final-hidden extraction
// ---------------------------------------------------------------------------
__global__ void fill_bias(float* __restrict__ out, const float* __restrict__ b)
{
    size_t i = (size_t)blockIdx.x * blockDim.x + threadIdx.x;
    if (i < (size_t)BT * OO) out[i] = b[i & (OO - 1)];
}

__global__ void write_finals(float* __restrict__ out)
{
    int i = blockIdx.x * blockDim.x + threadIdx.x;  // 0 .. 2*L*B*H-1
    int j = i & (HH - 1);
    int b = (i >> 10) & (BB - 1);
    int l = (i >> 16) & 1;
    int d = i >> 17;                                 // 0 = fw_h, 1 = bw_h
    const float* y = (l == 0) ? g_y0[d] : g_y1[d];
    int t = d ? 0 : (TT - 1);
    out[(size_t)BT * OO + i] = y[((size_t)b * TT + t) * HH + j];
}

// ---------------------------------------------------------------------------
// Launch sequence (graph-capturable: ~12 kernel launches, no allocs)
// ---------------------------------------------------------------------------
extern "C" void kernel_launch(void* const* d_in, const int* in_sizes, int n_in,
                              void* d_out, int out_size)
{
    const float* x       = (const float*)d_in[0];
    const float* fw_Wx0  = (const float*)d_in[1];
    const float* fw_Wh0  = (const float*)d_in[2];
    const float* fw_bx0  = (const float*)d_in[3];
    const float* fw_bh0  = (const float*)d_in[4];
    const float* fw_Wx1  = (const float*)d_in[5];
    const float* fw_Wh1  = (const float*)d_in[6];
    const float* fw_bx1  = (const float*)d_in[7];
    const float* fw_bh1  = (const float*)d_in[8];
    const float* bw_Wx0  = (const float*)d_in[9];
    const float* bw_Wh0  = (const float*)d_in[10];
    const float* bw_bx0  = (const float*)d_in[11];
    const float* bw_bh0  = (const float*)d_in[12];
    const float* bw_Wx1  = (const float*)d_in[13];
    const float* bw_Wh1  = (const float*)d_in[14];
    const float* bw_bx1  = (const float*)d_in[15];
    const float* bw_bh1  = (const float*)d_in[16];
    const float* fc_W    = (const float*)d_in[17];
    const float* fc_b    = (const float*)d_in[18];
    float* out = (float*)d_out;

    cudaFuncSetAttribute(gru_layer, cudaFuncAttributeMaxDynamicSharedMemorySize,
                         SMEM_BYTES);

    void* p;
    cudaGetSymbolAddress(&p, g_gx);
    float* gx0 = (float*)p;
    float* gx1 = gx0 + (size_t)BT * G3;
    cudaGetSymbolAddress(&p, g_y0);
    float* y00 = (float*)p;
    float* y01 = y00 + (size_t)BT * HH;
    cudaGetSymbolAddress(&p, g_y1);
    float* y10 = (float*)p;
    float* y11 = y10 + (size_t)BT * HH;

    dim3 ggx(G3 / 128, BT / 128);   // (24, 256)
    dim3 gfc(OO / 128, BT / 128);   // (4, 256)

    // Layer 0 input gates
    gemm_tf32<<<ggx, 256>>>(x, fw_Wx0, gx0, BT, G3, DD, 0);
    gemm_tf32<<<ggx, 256>>>(x, bw_Wx0, gx1, BT, G3, DD, 0);

    // Layer 0 recurrence (persistent, both dirs)
    reset_bar<<<1, 1>>>();
    gru_layer<<<NBLK, 256, SMEM_BYTES>>>(fw_Wh0, bw_Wh0, fw_bx0, fw_bh0,
                                         bw_bx0, bw_bh0, y00, y01);

    // Layer 1 input gates
    gemm_tf32<<<ggx, 256>>>(y00, fw_Wx1, gx0, BT, G3, HH, 0);
    gemm_tf32<<<ggx, 256>>>(y01, bw_Wx1, gx1, BT, G3, HH, 0);

    // Layer 1 recurrence
    reset_bar<<<1, 1>>>();
    gru_layer<<<NBLK, 256, SMEM_BYTES>>>(fw_Wh1, bw_Wh1, fw_bx1, fw_bh1,
                                         bw_bx1, bw_bh1, y10, y11);

    // FC: out = [fw_y1, bw_y1] @ fc_W + fc_b  (split-K over the two halves)
    fill_bias<<<((size_t)BT * OO + 255) / 256, 256>>>(out, fc_b);
    gemm_tf32<<<gfc, 256>>>(y10, fc_W,                   out, BT, OO, HH, 1);
    gemm_tf32<<<gfc, 256>>>(y11, fc_W + (size_t)HH * OO, out, BT, OO, HH, 1);

    // Final hidden states: fw_h [L,B,H] then bw_h [L,B,H]
    write_finals<<<(2 * LL * BB * HH) / 256, 256>>>(out);
}

// round 14
// speedup vs baseline: 1.1065x; 1.0311x over previous
#include <cuda_runtime.h>
#include <mma.h>
#include <cstdint>
#include <cstddef>

using namespace nvcuda;

// Problem dims
#define BB   64
#define TT   512
#define DD   512
#define HH   1024
#define OO   512
#define LL   2
#define G3   (3 * HH)          // 3072
#define BT   (BB * TT)         // 32768

#define NBLK  128              // persistent blocks (64 per direction)
#define NBLKD 64               // blocks per direction

// ---------------------------------------------------------------------------
// Scratch (static device memory; allocation-free per harness rules)
// ---------------------------------------------------------------------------
__device__ float g_gx[2][(size_t)BT * G3];       // per-dir input gates [BT, 3H]
__device__ float g_y0[2][(size_t)BT * HH];       // layer-0 outputs per dir
__device__ float g_y1[2][(size_t)BT * HH];       // layer-1 outputs per dir
__device__ float g_h[2][3][HH * BB];             // TRANSPOSED h, TRIPLE buffered
// monotonic sync counters, each on its own 128B line
__device__ unsigned g_stage_done[2][32];         // [dir][0]: blocks-finished-staging
__device__ unsigned g_h_ready[2][4][32];         // [dir][quarter][0]: h writes

__global__ void reset_bar()
{
    for (int d = 0; d < 2; d++) {
        g_stage_done[d][0] = 0;
        for (int q = 0; q < 4; q++) g_h_ready[d][q][0] = 0;
    }
}

__device__ __forceinline__ float4 tf32x4(float4 v)
{
    return make_float4(wmma::__float_to_tf32(v.x), wmma::__float_to_tf32(v.y),
                       wmma::__float_to_tf32(v.z), wmma::__float_to_tf32(v.w));
}

__device__ __forceinline__ void mma_tf32(float& c0, float& c1, float& c2, float& c3,
                                         uint32_t a0, uint32_t a1, uint32_t a2,
                                         uint32_t a3, uint32_t b0, uint32_t b1)
{
    asm volatile("mma.sync.aligned.m16n8k8.row.col.f32.tf32.tf32.f32 "
                 "{%0,%1,%2,%3}, {%4,%5,%6,%7}, {%8,%9}, {%0,%1,%2,%3};"
                 : "+f"(c0), "+f"(c1), "+f"(c2), "+f"(c3)
                 : "r"(a0), "r"(a1), "r"(a2), "r"(a3), "r"(b0), "r"(b1));
}

// ---------------------------------------------------------------------------
// Generic TF32 WMMA GEMM v2: 2-stage smem ping-pong, ONE syncthreads/k-iter.
// C[M,N] (+)= A[M,K] @ B[K,N]; 128x128 tile, BK=16, 256 threads.
// ---------------------------------------------------------------------------
__global__ void __launch_bounds__(256, 2)
gemm_tf32(const float* __restrict__ A, const float* __restrict__ Bg,
          float* __restrict__ C, int M, int N, int K, int accumulate)
{
    __shared__ float As[2][16][132];
    __shared__ float Bs[2][16][132];

    const int bm   = blockIdx.y * 128;
    const int bn   = blockIdx.x * 128;
    const int tid  = threadIdx.x;
    const int warp = tid >> 5;
    const int wm   = (warp & 3) * 32;
    const int wn   = (warp >> 2) * 64;

    wmma::fragment<wmma::accumulator, 16, 16, 8, float> acc[2][4];
#pragma unroll
    for (int i = 0; i < 2; i++)
#pragma unroll
        for (int j = 0; j < 4; j++)
            wmma::fill_fragment(acc[i][j], 0.0f);

    const int lm  = tid & 127;
    const int lkh = (tid >> 7) * 8;
    const int bk0 = (tid + 0 * 256) >> 5, bn0 = ((tid + 0 * 256) & 31) * 4;
    const int bk1 = (tid + 1 * 256) >> 5, bn1 = ((tid + 1 * 256) & 31) * 4;

    const float* ap0 = A + (size_t)(bm + lm) * K + lkh;

    // preload + stage k0 = 0
    {
        float4 a0 = tf32x4(*(const float4*)(ap0));
        float4 a1 = tf32x4(*(const float4*)(ap0 + 4));
        As[0][lkh + 0][lm] = a0.x; As[0][lkh + 1][lm] = a0.y;
        As[0][lkh + 2][lm] = a0.z; As[0][lkh + 3][lm] = a0.w;
        As[0][lkh + 4][lm] = a1.x; As[0][lkh + 5][lm] = a1.y;
        As[0][lkh + 6][lm] = a1.z; As[0][lkh + 7][lm] = a1.w;
        *(float4*)&Bs[0][bk0][bn0] = tf32x4(*(const float4*)(Bg + (size_t)bk0 * N + bn + bn0));
        *(float4*)&Bs[0][bk1][bn1] = tf32x4(*(const float4*)(Bg + (size_t)bk1 * N + bn + bn1));
    }
    __syncthreads();

    int st = 0;
    for (int k0 = 0; k0 < K; k0 += 16) {
        const bool more = (k0 + 16 < K);
        float4 na0, na1, nb0, nb1;
        if (more) {
            const float* apn = ap0 + k0 + 16;
            na0 = *(const float4*)(apn);
            na1 = *(const float4*)(apn + 4);
            nb0 = *(const float4*)(Bg + (size_t)(k0 + 16 + bk0) * N + bn + bn0);
            nb1 = *(const float4*)(Bg + (size_t)(k0 + 16 + bk1) * N + bn + bn1);
        }

#pragma unroll
        for (int kk = 0; kk < 16; kk += 8) {
            wmma::fragment<wmma::matrix_a, 16, 16, 8, wmma::precision::tf32,
                           wmma::col_major> af[2];
#pragma unroll
            for (int i = 0; i < 2; i++)
                wmma::load_matrix_sync(af[i], &As[st][kk][wm + i * 16], 132);
#pragma unroll
            for (int j = 0; j < 4; j++) {
                wmma::fragment<wmma::matrix_b, 16, 16, 8, wmma::precision::tf32,
                               wmma::row_major> bf;
                wmma::load_matrix_sync(bf, &Bs[st][kk][wn + j * 16], 132);
#pragma unroll
                for (int i = 0; i < 2; i++)
                    wmma::mma_sync(acc[i][j], af[i], bf, acc[i][j]);
            }
        }

        if (more) {
            const int ns = st ^ 1;
            float4 a0 = tf32x4(na0), a1 = tf32x4(na1);
            As[ns][lkh + 0][lm] = a0.x; As[ns][lkh + 1][lm] = a0.y;
            As[ns][lkh + 2][lm] = a0.z; As[ns][lkh + 3][lm] = a0.w;
            As[ns][lkh + 4][lm] = a1.x; As[ns][lkh + 5][lm] = a1.y;
            As[ns][lkh + 6][lm] = a1.z; As[ns][lkh + 7][lm] = a1.w;
            *(float4*)&Bs[ns][bk0][bn0] = tf32x4(nb0);
            *(float4*)&Bs[ns][bk1][bn1] = tf32x4(nb1);
        }
        __syncthreads();
        st ^= 1;
    }

#pragma unroll
    for (int i = 0; i < 2; i++)
#pragma unroll
        for (int j = 0; j < 4; j++) {
            float* cp = C + (size_t)(bm + wm + i * 16) * N + bn + wn + j * 16;
            if (accumulate) {
                wmma::fragment<wmma::accumulator, 16, 16, 8, float> cf;
                wmma::load_matrix_sync(cf, cp, N, wmma::mem_row_major);
#pragma unroll
                for (int e = 0; e < cf.num_elements; e++)
                    acc[i][j].x[e] += cf.x[e];
            }
            wmma::store_matrix_sync(cp, acc[i][j], N, wmma::mem_row_major);
        }
}

// ---------------------------------------------------------------------------
// Persistent GRU layer kernel v9: v8 core + TRIPLE-buffered h.
//   consumer wait (data dep):  h_ready[dir][ki] >= 16*s      (unchanged)
//   producer wait (anti dep):  stage_done[dir]  >= 64*(s-1)  (one step slack)
// Producer wait moved after the y store so pointwise math overlaps it.
// ---------------------------------------------------------------------------
#define WHS_LD  1028                 // floats per WhsT row
#define WHS_F   (48 * WHS_LD)        // 49344 floats
#define OVL_F   6144                 // staging (4608) / 2 partial regions (6144)
#define SMEM_BYTES ((WHS_F + OVL_F) * 4)   // 221952 B

__global__ void __launch_bounds__(256, 1)
gru_layer(const float* __restrict__ Wh_fw, const float* __restrict__ Wh_bw,
          const float* __restrict__ bx_fw, const float* __restrict__ bh_fw,
          const float* __restrict__ bx_bw, const float* __restrict__ bh_bw,
          float* __restrict__ y_fw, float* __restrict__ y_bw)
{
    extern __shared__ float smem[];
    float* WhsT = smem;            // [48][1028] tf32, WhsT[n][k]
    float* XB   = smem + WHS_F;    // overlay: staging / partial regions

    const int bid = blockIdx.x;
    const int dir = bid >> 6;          // 0 = fw, 1 = bw
    const int bd  = bid & 63;          // block within direction
    const int c0  = bd * 16;           // h-column base
    const int myq = bd >> 4;           // the k-quarter this block's h-cols feed

    const float* Wh = dir ? Wh_bw : Wh_fw;
    const float* bx = dir ? bx_bw : bx_fw;
    const float* bh = dir ? bh_bw : bh_fw;
    float*       y  = dir ? y_bw  : y_fw;
    const float* gx = g_gx[dir];

    const int tid  = threadIdx.x;
    const int warp = tid >> 5;
    const int lane = tid & 31;
    const int ki   = warp >> 1;        // k quarter (256)
    const int mi   = warp & 1;         // m half (32 rows)
    const int lg   = lane >> 2;        // mma groupID
    const int lt   = lane & 3;         // mma threadID-in-group

    float* mybuf = XB + warp * 576;    // 2 x [8k][36m] private staging

    volatile unsigned* vstage = &g_stage_done[dir][0];
    volatile unsigned* vready = &g_h_ready[dir][ki][0];

    const uint32_t whs_u32 = (uint32_t)__cvta_generic_to_shared(WhsT);
    const int lmg = lane >> 3;
    const int lmr = lane & 7;
    uint32_t ldm_off[3];
#pragma unroll
    for (int q = 0; q < 3; q++)
        ldm_off[q] = (uint32_t)((q * 16 + ((lmg >> 1) & 1) * 8 + lmr) * WHS_LD
                                + (lmg & 1) * 4);

    // ---- stage WhT slice into SMEM, tf32-rounded (once) ----
    for (int i = tid; i < 48 * HH; i += 256) {
        int k = i / 48;
        int n = i - k * 48;
        WhsT[n * WHS_LD + k] =
            wmma::__float_to_tf32(Wh[(size_t)k * G3 + (n >> 4) * HH + c0 + (n & 15)]);
    }

    // ---- per-thread pointwise constants ----
    const int pm  = tid >> 2;          // batch row (0..63)
    const int pj  = (tid & 3) * 4;     // 4 consecutive cols
    const int phc = c0 + pj;
    float br[4], bz[4], bxn_[4], bhn_[4];
#pragma unroll
    for (int q = 0; q < 4; q++) {
        int hc = phc + q;
        br[q]   = bx[hc] + bh[hc];
        bz[q]   = bx[HH + hc] + bh[HH + hc];
        bxn_[q] = bx[2 * HH + hc];
        bhn_[q] = bh[2 * HH + hc];
    }
    __syncthreads();

    // staging coords within a warp's [8k][32m] chunk
    const int sk = lane >> 2;          // 0..7  (k within chunk)
    const int sm = (lane & 3) * 8;     // m offset within 32

    for (int s = 0; s < TT; s++) {
        const int t = dir ? (TT - 1 - s) : s;
        const float* hT  = g_h[dir][(s + 2) % 3];   // h_{s-1}
        float*       hTw = g_h[dir][s % 3];         // h_s

        // ---- pointwise prefetch (own-block y + streaming gx; no sync dep) ----
        float4 pxr, pxz, pxn, php;
        {
            const float* gp = gx + ((size_t)pm * TT + t) * G3 + phc;
            pxr = __ldcs((const float4*)gp);
            pxz = __ldcs((const float4*)(gp + HH));
            pxn = __ldcs((const float4*)(gp + 2 * HH));
            if (s > 0) {
                const int tp = dir ? (t + 1) : (t - 1);
                php = *(const float4*)(y + ((size_t)pm * TT + tp) * HH + phc);
            } else {
                php = make_float4(0.f, 0.f, 0.f, 0.f);
            }
        }

        float acc[2][6][4];
#pragma unroll
        for (int f = 0; f < 2; f++)
#pragma unroll
            for (int n = 0; n < 6; n++)
#pragma unroll
                for (int e = 0; e < 4; e++)
                    acc[f][n][e] = 0.f;

        if (s > 0) {
            // ---- consumer wait: my k-quarter's 16 producers done h_{s-1} ----
            if (lane == 0) {
                const unsigned tgt = 16u * (unsigned)s;
                while (*vready < tgt) __nanosleep(32);
            }
            __syncwarp();

            const float* hsrc = hT + (size_t)(ki * 256 + sk) * BB + mi * 32 + sm;
            float4 P[3][2];
#pragma unroll
            for (int c = 0; c < 3; c++) {
                P[c][0] = __ldcg((const float4*)(hsrc + c * 8 * BB));
                P[c][1] = __ldcg((const float4*)(hsrc + c * 8 * BB + 4));
            }
            {
                float* d = mybuf + sk * 36 + sm;
                *(float4*)(d)     = P[0][0];
                *(float4*)(d + 4) = P[0][1];
            }
            __syncwarp();

#pragma unroll
            for (int c = 0; c < 32; c++) {
                if (c < 31) {
                    float* d = mybuf + ((c + 1) & 1) * 288 + sk * 36 + sm;
                    *(float4*)(d)     = P[(c + 1) % 3][0];
                    *(float4*)(d + 4) = P[(c + 1) % 3][1];
                }
                if (c < 29) {
                    P[c % 3][0] = __ldcg((const float4*)(hsrc + (c + 3) * 8 * BB));
                    P[c % 3][1] = __ldcg((const float4*)(hsrc + (c + 3) * 8 * BB + 4));
                }

                // ---- A fragments (scalar LDS from [k][m] staging) ----
                const float* bp = mybuf + (c & 1) * 288;
                uint32_t a[2][4];
#pragma unroll
                for (int f = 0; f < 2; f++) {
                    a[f][0] = __float_as_uint(bp[lt * 36 + f * 16 + lg]);
                    a[f][1] = __float_as_uint(bp[lt * 36 + f * 16 + lg + 8]);
                    a[f][2] = __float_as_uint(bp[(lt + 4) * 36 + f * 16 + lg]);
                    a[f][3] = __float_as_uint(bp[(lt + 4) * 36 + f * 16 + lg + 8]);
                }

                // ---- B fragments: 3x ldmatrix.x4 on WhsT rows ----
                const uint32_t kb = (uint32_t)(ki * 256 + c * 8);
                uint32_t b[3][4];
#pragma unroll
                for (int q = 0; q < 3; q++) {
                    uint32_t addr = whs_u32 + (ldm_off[q] + kb) * 4u;
                    asm volatile(
                        "ldmatrix.sync.aligned.m8n8.x4.shared.b16 "
                        "{%0,%1,%2,%3}, [%4];"
                        : "=r"(b[q][0]), "=r"(b[q][1]), "=r"(b[q][2]), "=r"(b[q][3])
                        : "r"(addr));
                }

                // ---- 12 mma.m16n8k8 ----
#pragma unroll
                for (int f = 0; f < 2; f++)
#pragma unroll
                    for (int n = 0; n < 6; n++)
                        mma_tf32(acc[f][n][0], acc[f][n][1], acc[f][n][2], acc[f][n][3],
                                 a[f][0], a[f][1], a[f][2], a[f][3],
                                 b[n >> 1][(n & 1) * 2], b[n >> 1][(n & 1) * 2 + 1]);
                __syncwarp();
            }
        }
        __syncthreads();   // staging reads complete; overlay becomes partials

        // this block finished consuming h_{s-1}
        if (tid == 0) atomicAdd(&g_stage_done[dir][0], 1u);

        // ---- pairwise k pre-reduction into 2 regions (raw acc layout) ----
        if (ki >= 2) {
            float* dst = XB + (ki - 2) * 3072;
#pragma unroll
            for (int f = 0; f < 2; f++)
#pragma unroll
                for (int n = 0; n < 6; n++) {
                    float* p = dst + (mi * 32 + f * 16 + lg) * 48 + n * 8 + 2 * lt;
                    *(float2*)p          = make_float2(acc[f][n][0], acc[f][n][1]);
                    *(float2*)(p + 8*48) = make_float2(acc[f][n][2], acc[f][n][3]);
                }
        }
        __syncthreads();
        if (ki < 2) {
            float* dst = XB + ki * 3072;
#pragma unroll
            for (int f = 0; f < 2; f++)
#pragma unroll
                for (int n = 0; n < 6; n++) {
                    float* p = dst + (mi * 32 + f * 16 + lg) * 48 + n * 8 + 2 * lt;
                    float2 lo = *(float2*)p;
                    float2 hi = *(float2*)(p + 8*48);
                    lo.x += acc[f][n][0]; lo.y += acc[f][n][1];
                    hi.x += acc[f][n][2]; hi.y += acc[f][n][3];
                    *(float2*)p          = lo;
                    *(float2*)(p + 8*48) = hi;
                }
        }
        __syncthreads();

        // ---- pointwise GRU update: thread -> (pm, 4 cols at pj) ----
        {
            const float* Gr = XB + pm * 48 + pj;
            float4 gr0 = *(const float4*)(Gr);
            float4 gr1 = *(const float4*)(Gr + 3072);
            float4 gz0 = *(const float4*)(Gr + 16);
            float4 gz1 = *(const float4*)(Gr + 16 + 3072);
            float4 gn0 = *(const float4*)(Gr + 32);
            float4 gn1 = *(const float4*)(Gr + 32 + 3072);

            float hv[4];
#pragma unroll
            for (int q = 0; q < 4; q++) {
                float gr = ((const float*)&gr0)[q] + ((const float*)&gr1)[q];
                float gz = ((const float*)&gz0)[q] + ((const float*)&gz1)[q];
                float gn = ((const float*)&gn0)[q] + ((const float*)&gn1)[q];
                float xr = ((const float*)&pxr)[q];
                float xz = ((const float*)&pxz)[q];
                float xn = ((const float*)&pxn)[q];
                float hp = ((const float*)&php)[q];
                float r = 1.f / (1.f + __expf(-(xr + br[q] + gr)));
                float z = 1.f / (1.f + __expf(-(xz + bz[q] + gz)));
                float n = tanhf(xn + bxn_[q] + r * (gn + bhn_[q]));
                hv[q] = (1.f - z) * n + z * hp;
            }
            // y write has no anti-dependency -> before the producer wait
            *(float4*)(y + ((size_t)pm * TT + t) * HH + phc) =
                make_float4(hv[0], hv[1], hv[2], hv[3]);

            // ---- producer wait (anti-dep, 1 step slack): all blocks past
            //      staging of step s-2 before overwriting h_{s-3} ----
            if (s > 1) {
                if (lane == 0) {
                    const unsigned tgt = 64u * (unsigned)(s - 1);
                    while (*vstage < tgt) __nanosleep(32);
                }
                __syncwarp();
            }

#pragma unroll
            for (int q = 0; q < 4; q++)
                __stcg(&hTw[(size_t)(phc + q) * BB + pm],
                       wmma::__float_to_tf32(hv[q]));
        }

        // ---- publish h_s for my quarter ----
        __syncthreads();
        if (tid == 0) {
            __threadfence();
            atomicAdd(&g_h_ready[dir][myq][0], 1u);
        }
    }
}

// ---------------------------------------------------------------------------
// FC bias prefill + final-hidden extraction
// ---------------------------------------------------------------------------
__global__ void fill_bias(float* __restrict__ out, const float* __restrict__ b)
{
    size_t i = (size_t)blockIdx.x * blockDim.x + threadIdx.x;
    if (i < (size_t)BT * OO) out[i] = b[i & (OO - 1)];
}

__global__ void write_finals(float* __restrict__ out)
{
    int i = blockIdx.x * blockDim.x + threadIdx.x;  // 0 .. 2*L*B*H-1
    int j = i & (HH - 1);
    int b = (i >> 10) & (BB - 1);
    int l = (i >> 16) & 1;
    int d = i >> 17;                                 // 0 = fw_h, 1 = bw_h
    const float* y = (l == 0) ? g_y0[d] : g_y1[d];
    int t = d ? 0 : (TT - 1);
    out[(size_t)BT * OO + i] = y[((size_t)b * TT + t) * HH + j];
}

// ---------------------------------------------------------------------------
// Launch sequence (graph-capturable: ~12 kernel launches, no allocs)
// ---------------------------------------------------------------------------
extern "C" void kernel_launch(void* const* d_in, const int* in_sizes, int n_in,
                              void* d_out, int out_size)
{
    const float* x       = (const float*)d_in[0];
    const float* fw_Wx0  = (const float*)d_in[1];
    const float* fw_Wh0  = (const float*)d_in[2];
    const float* fw_bx0  = (const float*)d_in[3];
    const float* fw_bh0  = (const float*)d_in[4];
    const float* fw_Wx1  = (const float*)d_in[5];
    const float* fw_Wh1  = (const float*)d_in[6];
    const float* fw_bx1  = (const float*)d_in[7];
    const float* fw_bh1  = (const float*)d_in[8];
    const float* bw_Wx0  = (const float*)d_in[9];
    const float* bw_Wh0  = (const float*)d_in[10];
    const float* bw_bx0  = (const float*)d_in[11];
    const float* bw_bh0  = (const float*)d_in[12];
    const float* bw_Wx1  = (const float*)d_in[13];
    const float* bw_Wh1  = (const float*)d_in[14];
    const float* bw_bx1  = (const float*)d_in[15];
    const float* bw_bh1  = (const float*)d_in[16];
    const float* fc_W    = (const float*)d_in[17];
    const float* fc_b    = (const float*)d_in[18];
    float* out = (float*)d_out;

    cudaFuncSetAttribute(gru_layer, cudaFuncAttributeMaxDynamicSharedMemorySize,
                         SMEM_BYTES);

    void* p;
    cudaGetSymbolAddress(&p, g_gx);
    float* gx0 = (float*)p;
    float* gx1 = gx0 + (size_t)BT * G3;
    cudaGetSymbolAddress(&p, g_y0);
    float* y00 = (float*)p;
    float* y01 = y00 + (size_t)BT * HH;
    cudaGetSymbolAddress(&p, g_y1);
    float* y10 = (float*)p;
    float* y11 = y10 + (size_t)BT * HH;

    dim3 ggx(G3 / 128, BT / 128);   // (24, 256)
    dim3 gfc(OO / 128, BT / 128);   // (4, 256)

    // Layer 0 input gates
    gemm_tf32<<<ggx, 256>>>(x, fw_Wx0, gx0, BT, G3, DD, 0);
    gemm_tf32<<<ggx, 256>>>(x, bw_Wx0, gx1, BT, G3, DD, 0);

    // Layer 0 recurrence (persistent, both dirs)
    reset_bar<<<1, 1>>>();
    gru_layer<<<NBLK, 256, SMEM_BYTES>>>(fw_Wh0, bw_Wh0, fw_bx0, fw_bh0,
                                         bw_bx0, bw_bh0, y00, y01);

    // Layer 1 input gates
    gemm_tf32<<<ggx, 256>>>(y00, fw_Wx1, gx0, BT, G3, HH, 0);
    gemm_tf32<<<ggx, 256>>>(y01, bw_Wx1, gx1, BT, G3, HH, 0);

    // Layer 1 recurrence
    reset_bar<<<1, 1>>>();
    gru_layer<<<NBLK, 256, SMEM_BYTES>>>(fw_Wh1, bw_Wh1, fw_bx1, fw_bh1,
                                         bw_bx1, bw_bh1, y10, y11);

    // FC: out = [fw_y1, bw_y1] @ fc_W + fc_b  (split-K over the two halves)
    fill_bias<<<((size_t)BT * OO + 255) / 256, 256>>>(out, fc_b);
    gemm_tf32<<<gfc, 256>>>(y10, fc_W,                   out, BT, OO, HH, 1);
    gemm_tf32<<<gfc, 256>>>(y11, fc_W + (size_t)HH * OO, out, BT, OO, HH, 1);

    // Final hidden states: fw_h [L,B,H] then bw_h [L,B,H]
    write_finals<<<(2 * LL * BB * HH) / 256, 256>>>(out);
}